// round 5
// baseline (speedup 1.0000x reference)
#include <cuda_runtime.h>

// Folded weights: Weff[ci][r3][co], r3 = rd*9+rh*3+rw, scaled by gamma/sqrt(var+eps)/64
__device__ float g_wf[16 * 27 * 32];
// Per-channel constant: bias*scale + beta - mean*scale
__device__ float g_cb[32];

// ---------------------------------------------------------------------------
// Prep: fold ConvTranspose kernel taps + BN affine + pool 1/64 into Weff.
// Tap sets per residue r (from z = 2i - 1 + k, z-offset in [0,3]):
//   T(0) = {1,2}, T(1) = {0,1,2}, T(2) = {0}
// ---------------------------------------------------------------------------
__global__ void prep_kernel(const float* __restrict__ w,
                            const float* __restrict__ bias,
                            const float* __restrict__ gamma,
                            const float* __restrict__ beta,
                            const float* __restrict__ mean,
                            const float* __restrict__ var) {
    int idx = blockIdx.x * blockDim.x + threadIdx.x;
    if (idx >= 16 * 27 * 32) return;

    int co = idx & 31;
    int r3 = (idx >> 5) % 27;
    int ci = idx / (27 * 32);
    int rd = r3 / 9, rh = (r3 / 3) % 3, rw = r3 % 3;

    const int st[3] = {1, 0, 0};
    const int en[3] = {3, 3, 1};

    // torch ConvTranspose3d weight layout: (Cin, Cout, kd, kh, kw)
    const float* wb = w + ((size_t)(ci * 32 + co)) * 27;
    float s = 0.f;
    for (int kd = st[rd]; kd < en[rd]; ++kd)
        for (int kh = st[rh]; kh < en[rh]; ++kh)
            for (int kw = st[rw]; kw < en[rw]; ++kw)
                s += wb[kd * 9 + kh * 3 + kw];

    float sc = gamma[co] * rsqrtf(var[co] + 1e-5f);
    g_wf[(ci * 27 + r3) * 32 + co] = s * sc * (1.f / 64.f);

    if (idx < 32) {
        float sc2 = gamma[idx] * rsqrtf(var[idx] + 1e-5f);
        g_cb[idx] = bias[idx] * sc2 + beta[idx] - mean[idx] * sc2;
    }
}

// ---------------------------------------------------------------------------
// Main: out[b,co,od,oh,ow] = sum_{ci, r3} x[b,ci,2od+rd,2oh+rh,2ow+rw]*Weff + C
// Warp = one (b, od, oh); lane = co; 11 ow accumulators in registers.
// x rows are 24 floats (96B, 16B-aligned) -> 6 uniform float4 loads/row.
// Grid 242 blocks x 128 threads = 968 warps (8*11*11 triples exactly).
// ---------------------------------------------------------------------------
__global__ __launch_bounds__(128)
void conv_fused_kernel(const float* __restrict__ x, float* __restrict__ out) {
    const int lane = threadIdx.x & 31;                 // co
    const int gw = (blockIdx.x << 2) + (threadIdx.x >> 5);  // 0..967
    const int b = gw / 121;
    const int rem = gw - b * 121;
    const int od = rem / 11;
    const int oh = rem - od * 11;

    float acc[11];
#pragma unroll
    for (int i = 0; i < 11; ++i) acc[i] = 0.f;

    // x layout: (B, 16, 24, 24, 24); plane = 576, channel = 13824
    const float* xb = x + ((size_t)b * 16) * 13824 + (2 * od) * 576 + (2 * oh) * 24;
    const float* wp = g_wf + lane;

#pragma unroll 1
    for (int ci = 0; ci < 16; ++ci) {
        float w[27];
#pragma unroll
        for (int r = 0; r < 27; ++r) w[r] = __ldg(wp + (ci * 27 + r) * 32);

        const float* xc = xb + ci * 13824;
#pragma unroll
        for (int rd = 0; rd < 3; ++rd) {
#pragma unroll
            for (int rh = 0; rh < 3; ++rh) {
                const float4* rp =
                    reinterpret_cast<const float4*>(xc + rd * 576 + rh * 24);
                float4 v0 = __ldg(rp + 0), v1 = __ldg(rp + 1), v2 = __ldg(rp + 2);
                float4 v3 = __ldg(rp + 3), v4 = __ldg(rp + 4), v5 = __ldg(rp + 5);
                float xr[24] = {v0.x, v0.y, v0.z, v0.w, v1.x, v1.y, v1.z, v1.w,
                                v2.x, v2.y, v2.z, v2.w, v3.x, v3.y, v3.z, v3.w,
                                v4.x, v4.y, v4.z, v4.w, v5.x, v5.y, v5.z, v5.w};
#pragma unroll
                for (int rw = 0; rw < 3; ++rw) {
                    const float wv = w[(rd * 3 + rh) * 3 + rw];
#pragma unroll
                    for (int ow = 0; ow < 11; ++ow)
                        acc[ow] = fmaf(wv, xr[2 * ow + rw], acc[ow]);
                }
            }
        }
    }

    const float cb = __ldg(&g_cb[lane]);
    // out layout: (8, 32, 11, 11, 11)
    float* op = out + (((size_t)(b * 32 + lane)) * 11 + od) * 121 + oh * 11;
#pragma unroll
    for (int ow = 0; ow < 11; ++ow) op[ow] = acc[ow] + cb;
}

extern "C" void kernel_launch(void* const* d_in, const int* in_sizes, int n_in,
                              void* d_out, int out_size) {
    const float* x     = (const float*)d_in[0];
    const float* w     = (const float*)d_in[1];
    const float* bias  = (const float*)d_in[2];
    const float* gamma = (const float*)d_in[3];
    const float* beta  = (const float*)d_in[4];
    const float* mean  = (const float*)d_in[5];
    const float* var   = (const float*)d_in[6];
    float* out = (float*)d_out;

    prep_kernel<<<(16 * 27 * 32 + 255) / 256, 256>>>(w, bias, gamma, beta, mean, var);
    conv_fused_kernel<<<242, 128>>>(x, out);
}

// round 6
// speedup vs baseline: 2.1820x; 2.1820x over previous
#include <cuda_runtime.h>

// Folded weights: Weff[ci][r3][co], r3 = rd*9+rh*3+rw, scaled by gamma/sqrt(var+eps)/64
__device__ float g_wf[16 * 27 * 32];
// Per-channel constant: bias*scale + beta - mean*scale
__device__ float g_cb[32];

// ---------------------------------------------------------------------------
// Prep: fold ConvTranspose taps + BN affine + pool 1/64 into Weff.
// Tap sets per residue r (z = 2i - 1 + k, z-offset in [0,3]):
//   T(0) = {1,2}, T(1) = {0,1,2}, T(2) = {0}
// ---------------------------------------------------------------------------
__global__ void prep_kernel(const float* __restrict__ w,
                            const float* __restrict__ bias,
                            const float* __restrict__ gamma,
                            const float* __restrict__ beta,
                            const float* __restrict__ mean,
                            const float* __restrict__ var) {
    int idx = blockIdx.x * blockDim.x + threadIdx.x;
    if (idx >= 16 * 27 * 32) return;

    int co = idx & 31;
    int r3 = (idx >> 5) % 27;
    int ci = idx / (27 * 32);
    int rd = r3 / 9, rh = (r3 / 3) % 3, rw = r3 % 3;

    const int st[3] = {1, 0, 0};
    const int en[3] = {3, 3, 1};

    const float* wb = w + ((size_t)(ci * 32 + co)) * 27;
    float s = 0.f;
    for (int kd = st[rd]; kd < en[rd]; ++kd)
        for (int kh = st[rh]; kh < en[rh]; ++kh)
            for (int kw = st[rw]; kw < en[rw]; ++kw)
                s += wb[kd * 9 + kh * 3 + kw];

    float sc = gamma[co] * rsqrtf(var[co] + 1e-5f);
    g_wf[(ci * 27 + r3) * 32 + co] = s * sc * (1.f / 64.f);

    if (idx < 32) {
        float sc2 = gamma[idx] * rsqrtf(var[idx] + 1e-5f);
        g_cb[idx] = bias[idx] * sc2 + beta[idx] - mean[idx] * sc2;
    }
}

// ---------------------------------------------------------------------------
// Main: block = one (b, od, oh). 128 threads.
//   Phase 1: coop-load x tile [16 ci][3 rd][3 rh][24 w] into smem (coalesced).
//   Phase 2: warp w computes ci in [4w, 4w+4); lane = co; acc[11] over ow.
//            x rows read from smem as broadcast LDS.128.
//   Phase 3: cross-warp reduce via smem, add per-channel constant, store.
// ---------------------------------------------------------------------------
__global__ __launch_bounds__(128)
void conv_fused_kernel(const float* __restrict__ x, float* __restrict__ out) {
    __shared__ __align__(16) float xs[16 * 9 * 24];   // 13824 B
    __shared__ float red[4][11 * 32];                 //  5632 B

    const int tid  = threadIdx.x;
    const int lane = tid & 31;    // co
    const int wid  = tid >> 5;    // warp in block

    const int gw  = blockIdx.x;          // 0..967
    const int b   = gw / 121;
    const int rem = gw - b * 121;
    const int od  = rem / 11;
    const int oh  = rem - od * 11;

    // ---- Phase 1: cooperative staging (864 float4 = 144 rows x 6) ----
    // x layout: (8, 16, 24, 24, 24); channel stride 13824, plane 576, row 24
    const float* xb = x + ((size_t)b * 16) * 13824 + (2 * od) * 576 + (2 * oh) * 24;
#pragma unroll
    for (int it = 0; it < 7; ++it) {
        int idx = tid + it * 128;
        if (idx < 864) {
            int row = idx / 6, q = idx - row * 6;    // row = ci*9 + rd*3 + rh
            int ci = row / 9, rr = row - ci * 9;
            int rd = rr / 3, rh = rr - rd * 3;
            float4 v = __ldg(reinterpret_cast<const float4*>(
                                 xb + ci * 13824 + rd * 576 + rh * 24) + q);
            reinterpret_cast<float4*>(xs)[idx] = v;  // xs[(ci*9+rr)*24 + q*4]
        }
    }
    __syncthreads();

    // ---- Phase 2: compute 4 ci per warp ----
    float acc[11];
#pragma unroll
    for (int i = 0; i < 11; ++i) acc[i] = 0.f;

    const float* wp = g_wf + lane;
#pragma unroll 1
    for (int cc = 0; cc < 4; ++cc) {
        const int ci = (wid << 2) + cc;
        float w[27];
#pragma unroll
        for (int r = 0; r < 27; ++r) w[r] = __ldg(wp + (ci * 27 + r) * 32);

        const float* xsc = xs + ci * 216;
#pragma unroll
        for (int rr = 0; rr < 9; ++rr) {
            const float4* rp = reinterpret_cast<const float4*>(xsc + rr * 24);
            float4 v0 = rp[0], v1 = rp[1], v2 = rp[2];
            float4 v3 = rp[3], v4 = rp[4], v5 = rp[5];
            float xr[24] = {v0.x, v0.y, v0.z, v0.w, v1.x, v1.y, v1.z, v1.w,
                            v2.x, v2.y, v2.z, v2.w, v3.x, v3.y, v3.z, v3.w,
                            v4.x, v4.y, v4.z, v4.w, v5.x, v5.y, v5.z, v5.w};
#pragma unroll
            for (int rw = 0; rw < 3; ++rw) {
                const float wv = w[rr * 3 + rw];
#pragma unroll
                for (int ow = 0; ow < 11; ++ow)
                    acc[ow] = fmaf(wv, xr[2 * ow + rw], acc[ow]);
            }
        }
    }

    // ---- Phase 3: cross-warp reduction + store ----
#pragma unroll
    for (int j = 0; j < 11; ++j) red[wid][j * 32 + lane] = acc[j];
    __syncthreads();

    const float cb = g_cb[lane];
    // out layout: (8, 32, 11, 11, 11)
    float* op = out + (((size_t)(b * 32 + lane)) * 11 + od) * 121 + oh * 11;
#pragma unroll 1
    for (int j = wid; j < 11; j += 4) {
        float s = red[0][j * 32 + lane] + red[1][j * 32 + lane] +
                  red[2][j * 32 + lane] + red[3][j * 32 + lane] + cb;
        op[j] = s;
    }
}

extern "C" void kernel_launch(void* const* d_in, const int* in_sizes, int n_in,
                              void* d_out, int out_size) {
    const float* x     = (const float*)d_in[0];
    const float* w     = (const float*)d_in[1];
    const float* bias  = (const float*)d_in[2];
    const float* gamma = (const float*)d_in[3];
    const float* beta  = (const float*)d_in[4];
    const float* mean  = (const float*)d_in[5];
    const float* var   = (const float*)d_in[6];
    float* out = (float*)d_out;

    prep_kernel<<<(16 * 27 * 32 + 255) / 256, 256>>>(w, bias, gamma, beta, mean, var);
    conv_fused_kernel<<<968, 128>>>(x, out);
}

// round 7
// speedup vs baseline: 3.3222x; 1.5225x over previous
#include <cuda_runtime.h>

typedef unsigned long long u64;

// Packed folded weights: {Weff[2p][r3][co], Weff[2p+1][r3][co]} as f32x2
// index: (pair*27 + r3)*32 + co
__device__ u64 g_wf2[8 * 27 * 32];
// Per-channel constant: bias*scale + beta - mean*scale
__device__ float g_cb[32];

// ---------------------------------------------------------------------------
// Prep: fold ConvTranspose taps + BN affine + pool 1/64 into packed Weff.
// Tap sets per residue r (z = 2i - 1 + k, z-offset in [0,3]):
//   T(0) = {1,2}, T(1) = {0,1,2}, T(2) = {0}
// ---------------------------------------------------------------------------
__global__ void prep_kernel(const float* __restrict__ w,
                            const float* __restrict__ bias,
                            const float* __restrict__ gamma,
                            const float* __restrict__ beta,
                            const float* __restrict__ mean,
                            const float* __restrict__ var) {
    int idx = blockIdx.x * blockDim.x + threadIdx.x;
    if (idx >= 16 * 27 * 32) return;

    int co = idx & 31;
    int r3 = (idx >> 5) % 27;
    int ci = idx / (27 * 32);
    int rd = r3 / 9, rh = (r3 / 3) % 3, rw = r3 % 3;

    const int st[3] = {1, 0, 0};
    const int en[3] = {3, 3, 1};

    const float* wb = w + ((size_t)(ci * 32 + co)) * 27;
    float s = 0.f;
    for (int kd = st[rd]; kd < en[rd]; ++kd)
        for (int kh = st[rh]; kh < en[rh]; ++kh)
            for (int kw = st[rw]; kw < en[rw]; ++kw)
                s += wb[kd * 9 + kh * 3 + kw];

    float sc = gamma[co] * rsqrtf(var[co] + 1e-5f);
    float val = s * sc * (1.f / 64.f);
    // packed layout: lo = even ci, hi = odd ci
    ((float*)g_wf2)[((((ci >> 1) * 27) + r3) * 32 + co) * 2 + (ci & 1)] = val;

    if (idx < 32) {
        float sc2 = gamma[idx] * rsqrtf(var[idx] + 1e-5f);
        g_cb[idx] = bias[idx] * sc2 + beta[idx] - mean[idx] * sc2;
    }
}

__device__ __forceinline__ void fma2(u64& d, u64 a, u64 b) {
    asm("fma.rn.f32x2 %0, %1, %2, %0;" : "+l"(d) : "l"(a), "l"(b));
}

// ---------------------------------------------------------------------------
// Main: block = one (b, od, oh). 256 threads = 8 warps.
//   Phase 1: coop-stage x as ci-pair-interleaved f32x2 tile
//            xs2[pair][rr][i] = {x[2p][..i], x[2p+1][..i]}   (13.8 KB)
//   Phase 2: warp p computes ci pair p; lane = co; 11 packed accumulators
//            over ow, fma.rn.f32x2 does both ci lanes at once.
//   Phase 3: unpack (lo+hi), cross-warp reduce via smem, add const, store.
// ---------------------------------------------------------------------------
__global__ __launch_bounds__(256)
void conv_fused_kernel(const float* __restrict__ x, float* __restrict__ out) {
    __shared__ __align__(16) u64 xs2[8 * 9 * 24];    // 13824 B
    __shared__ float red[8][11 * 32];                // 11264 B

    const int tid  = threadIdx.x;
    const int lane = tid & 31;   // co
    const int wid  = tid >> 5;   // ci pair

    const int gw  = blockIdx.x;          // 0..967
    const int b   = gw / 121;
    const int rem = gw - b * 121;
    const int od  = rem / 11;
    const int oh  = rem - od * 11;

    // ---- Phase 1: staging (432 tasks: pair x rr x q) ----
    // x layout: (8, 16, 24, 24, 24); channel 13824, plane 576, row 24
    const float* xb = x + ((size_t)b * 16) * 13824 + (2 * od) * 576 + (2 * oh) * 24;
#pragma unroll
    for (int it = 0; it < 2; ++it) {
        int t = tid + it * 256;
        if (t < 432) {
            int pair = t / 54, r2 = t - pair * 54;
            int rr = r2 / 6, q = r2 - rr * 6;
            int rd = rr / 3, rh = rr - rd * 3;
            const float* base = xb + (2 * pair) * 13824 + rd * 576 + rh * 24;
            float4 a  = __ldg(reinterpret_cast<const float4*>(base) + q);
            float4 bb = __ldg(reinterpret_cast<const float4*>(base + 13824) + q);
            float4* dst = reinterpret_cast<float4*>(xs2 + (pair * 9 + rr) * 24);
            dst[2 * q]     = make_float4(a.x, bb.x, a.y, bb.y);
            dst[2 * q + 1] = make_float4(a.z, bb.z, a.w, bb.w);
        }
    }
    __syncthreads();

    // ---- Phase 2: packed compute, one ci-pair per warp ----
    u64 acc[11];
#pragma unroll
    for (int i = 0; i < 11; ++i) acc[i] = 0ull;

    const u64* wp   = g_wf2 + (size_t)wid * 27 * 32 + lane;
    const u64* xrow = xs2 + wid * 9 * 24;

#pragma unroll
    for (int rr = 0; rr < 9; ++rr) {
        u64 w0 = __ldg(wp + (rr * 3 + 0) * 32);
        u64 w1 = __ldg(wp + (rr * 3 + 1) * 32);
        u64 w2 = __ldg(wp + (rr * 3 + 2) * 32);
        const ulonglong2* rp = reinterpret_cast<const ulonglong2*>(xrow + rr * 24);

        u64 xv[14];
        // chunk A: i = 0..11
#pragma unroll
        for (int k = 0; k < 6; ++k) {
            ulonglong2 t = rp[k];
            xv[2 * k] = t.x; xv[2 * k + 1] = t.y;
        }
#pragma unroll
        for (int ow = 0; ow < 5; ++ow) {
            fma2(acc[ow], w0, xv[2 * ow]);
            fma2(acc[ow], w1, xv[2 * ow + 1]);
            fma2(acc[ow], w2, xv[2 * ow + 2]);
        }
        fma2(acc[5], w0, xv[10]);
        fma2(acc[5], w1, xv[11]);
        // chunk B: i = 12..23 -> xv[2..13]
#pragma unroll
        for (int k = 0; k < 6; ++k) {
            ulonglong2 t = rp[6 + k];
            xv[2 * k + 2] = t.x; xv[2 * k + 3] = t.y;
        }
        fma2(acc[5], w2, xv[2]);  // i = 12
#pragma unroll
        for (int ow = 6; ow < 11; ++ow) {
            fma2(acc[ow], w0, xv[2 * ow - 10]);
            fma2(acc[ow], w1, xv[2 * ow - 9]);
            fma2(acc[ow], w2, xv[2 * ow - 8]);
        }
    }

    // ---- Phase 3: unpack + cross-warp reduce + store ----
#pragma unroll
    for (int ow = 0; ow < 11; ++ow) {
        float lo, hi;
        asm("mov.b64 {%0, %1}, %2;" : "=f"(lo), "=f"(hi) : "l"(acc[ow]));
        red[wid][ow * 32 + lane] = lo + hi;
    }
    __syncthreads();

    // out layout: (8, 32, 11, 11, 11)
#pragma unroll
    for (int it = 0; it < 2; ++it) {
        int j = tid + it * 256;
        if (j < 352) {
            float s = g_cb[j & 31];
#pragma unroll
            for (int w = 0; w < 8; ++w) s += red[w][j];
            int ow = j >> 5, co = j & 31;
            out[((size_t)(b * 32 + co)) * 1331 + od * 121 + oh * 11 + ow] = s;
        }
    }
}

extern "C" void kernel_launch(void* const* d_in, const int* in_sizes, int n_in,
                              void* d_out, int out_size) {
    const float* x     = (const float*)d_in[0];
    const float* w     = (const float*)d_in[1];
    const float* bias  = (const float*)d_in[2];
    const float* gamma = (const float*)d_in[3];
    const float* beta  = (const float*)d_in[4];
    const float* mean  = (const float*)d_in[5];
    const float* var   = (const float*)d_in[6];
    float* out = (float*)d_out;

    prep_kernel<<<(16 * 27 * 32 + 255) / 256, 256>>>(w, bias, gamma, beta, mean, var);
    conv_fused_kernel<<<968, 256>>>(x, out);
}